// round 8
// baseline (speedup 1.0000x reference)
#include <cuda_runtime.h>
#include <cstdint>

#define B_   2
#define SQ_  2048
#define SK_  512
#define HID_ 1024
#define NH_  16
#define HD_  64

// Scratch (static __device__ globals: allowed, no runtime allocation)
__device__ float g_Qt[B_*NH_*HD_*SQ_];   // [bh][d][q], pre-scaled by 1/8
__device__ float g_Kt[B_*NH_*HD_*SK_];   // [bh][d][k]
__device__ float g_V [B_*NH_*SK_*HD_];   // [bh][k][d]

// ===================== packed f32x2 helpers (FFMA2) ========================
static __device__ __forceinline__ uint64_t pack2(float lo, float hi) {
    uint64_t r;
    asm("mov.b64 %0, {%1, %2};" : "=l"(r) : "f"(lo), "f"(hi));
    return r;
}
static __device__ __forceinline__ uint64_t dup2(float v) { return pack2(v, v); }
static __device__ __forceinline__ void fma2(uint64_t& d, uint64_t a, uint64_t b) {
    asm("fma.rn.f32x2 %0, %1, %2, %0;" : "+l"(d) : "l"(a), "l"(b));
}
static __device__ __forceinline__ void unpack2(uint64_t v, float& lo, float& hi) {
    asm("mov.b64 {%0, %1}, %2;" : "=f"(lo), "=f"(hi) : "l"(v));
}

// ---------------------------------------------------------------------------
// Unified QKV projection GEMM (UNCHANGED — measured at FFMA2 floor ~300us):
// out = A(M x 1024) @ W^T. 384 CTAs: [0,256)=Q, [256,320)=K, [320,384)=V.
// ---------------------------------------------------------------------------
__global__ void __launch_bounds__(256)
gemm_all(const float* __restrict__ hs, const float* __restrict__ ehs,
         const float* __restrict__ Wq, const float* __restrict__ Wk,
         const float* __restrict__ Wv,
         float* __restrict__ pQ, float* __restrict__ pK, float* __restrict__ pV)
{
    __shared__ float As[16][128];
    __shared__ float Bs[16][128];

    const int bid = blockIdx.x;
    const float *A, *W;
    float* outp;
    int S, mode, lx, ly;
    float scale;
    if (bid < 256) {
        A = hs;  W = Wq; outp = pQ; S = SQ_; scale = 0.125f; mode = 1;
        lx = bid & 7; ly = bid >> 3;
    } else if (bid < 320) {
        int t = bid - 256;
        A = ehs; W = Wk; outp = pK; S = SK_; scale = 1.0f; mode = 1;
        lx = t & 7; ly = t >> 3;
    } else {
        int t = bid - 320;
        A = ehs; W = Wv; outp = pV; S = SK_; scale = 1.0f; mode = 0;
        lx = t & 7; ly = t >> 3;
    }
    const int m0 = ly * 128;
    const int n0 = lx * 128;

    const int tid = threadIdx.x;
    const int tx  = tid & 15;
    const int ty  = tid >> 4;

    uint64_t acc2[8][4];
    #pragma unroll
    for (int i = 0; i < 8; i++)
        #pragma unroll
        for (int j = 0; j < 4; j++) acc2[i][j] = 0ull;

    for (int kt = 0; kt < HID_ / 16; kt++) {
        const float* Ap = A + (size_t)m0 * HID_ + kt * 16;
        const float* Wp = W + (size_t)n0 * HID_ + kt * 16;
        #pragma unroll
        for (int p = 0; p < 2; p++) {
            int idx = tid + p * 256;          // 0..511
            int row = idx >> 2;               // 0..127
            int c4  = (idx & 3) << 2;         // 0,4,8,12
            float4 va = *(const float4*)(Ap + (size_t)row * HID_ + c4);
            As[c4 + 0][row] = va.x; As[c4 + 1][row] = va.y;
            As[c4 + 2][row] = va.z; As[c4 + 3][row] = va.w;
            float4 vb = *(const float4*)(Wp + (size_t)row * HID_ + c4);
            Bs[c4 + 0][row] = vb.x; Bs[c4 + 1][row] = vb.y;
            Bs[c4 + 2][row] = vb.z; Bs[c4 + 3][row] = vb.w;
        }
        __syncthreads();

        #pragma unroll
        for (int k = 0; k < 16; k++) {
            float4 a0 = *(float4*)&As[k][ty * 4];
            float4 a1 = *(float4*)&As[k][64 + ty * 4];
            float4 b0 = *(float4*)&Bs[k][tx * 4];
            float4 b1 = *(float4*)&Bs[k][64 + tx * 4];
            uint64_t bp[4] = {pack2(b0.x, b0.y), pack2(b0.z, b0.w),
                              pack2(b1.x, b1.y), pack2(b1.z, b1.w)};
            float av[8] = {a0.x, a0.y, a0.z, a0.w, a1.x, a1.y, a1.z, a1.w};
            #pragma unroll
            for (int i = 0; i < 8; i++) {
                uint64_t ai = dup2(av[i]);
                #pragma unroll
                for (int j = 0; j < 4; j++)
                    fma2(acc2[i][j], ai, bp[j]);
            }
        }
        __syncthreads();
    }

    float acc[8][8];
    #pragma unroll
    for (int i = 0; i < 8; i++)
        #pragma unroll
        for (int j = 0; j < 4; j++)
            unpack2(acc2[i][j], acc[i][j * 2], acc[i][j * 2 + 1]);

    if (mode == 0) {
        #pragma unroll
        for (int i = 0; i < 8; i++) {
            int m  = m0 + ((i < 4) ? (ty * 4 + i) : (64 + ty * 4 + (i - 4)));
            int bb = m / S;
            int s  = m - bb * S;
            #pragma unroll
            for (int jg = 0; jg < 2; jg++) {
                int n = n0 + jg * 64 + tx * 4;
                int h = n >> 6, d = n & 63;
                float4 v = make_float4(acc[i][jg*4+0], acc[i][jg*4+1],
                                       acc[i][jg*4+2], acc[i][jg*4+3]);
                *(float4*)&outp[(((size_t)bb * NH_ + h) * S + s) * HD_ + d] = v;
            }
        }
    } else {
        #pragma unroll
        for (int jg = 0; jg < 2; jg++) {
            #pragma unroll
            for (int j = 0; j < 4; j++) {
                int n = n0 + jg * 64 + tx * 4 + j;
                int h = n >> 6, d = n & 63;
                #pragma unroll
                for (int ig = 0; ig < 2; ig++) {
                    int m  = m0 + ig * 64 + ty * 4;
                    int bb = m / S;
                    int s  = m - bb * S;
                    float4 v = make_float4(acc[ig*4+0][jg*4+j] * scale,
                                           acc[ig*4+1][jg*4+j] * scale,
                                           acc[ig*4+2][jg*4+j] * scale,
                                           acc[ig*4+3][jg*4+j] * scale);
                    *(float4*)&outp[(((size_t)bb * NH_ + h) * HD_ + d) * S + s] = v;
                }
            }
        }
    }
}

// ---------------------------------------------------------------------------
// Fused attention. Per block = one (b, h, 64-query tile), 512 threads.
// Phase 1: scores = Qs^T Ks (scalar FFMA), kept in regs, raw copy -> d_out.
// Phase 2: register softmax (warp owns its 4 rows), P -> smem once.
// Phase 3: context = P @ V — NEW: k-split 2, 4q x 4d per thread, k stepped by
//          4 so both P and V come in as LDS.128 (16 wf per 64 FMA).
// Dynamic smem 182272 B.
// ---------------------------------------------------------------------------
__global__ void __launch_bounds__(512)
attn_kernel(const int* __restrict__ mask,
            float* __restrict__ out_ctx, float* __restrict__ out_scores)
{
    extern __shared__ float smf[];
    float* Qst  = smf;                      // [64][64]  (d-major)
    float* KV   = smf + 64 * 64;            // [64][128] K chunk OR [128][64] V chunk
    float* Ss   = KV + 64 * 128;            // [64][512]  (holds P)
    float* madd = Ss + 64 * 512;            // [512]

    const int tid = threadIdx.x;
    const int q0  = blockIdx.x * 64;
    const int h   = blockIdx.y;
    const int b   = blockIdx.z;
    const int bh  = b * NH_ + h;

    {
        const float* src = g_Qt + (size_t)bh * HD_ * SQ_;
        #pragma unroll
        for (int p = 0; p < 2; p++) {
            int idx = tid + p * 512;
            int d = idx >> 4;
            int c = (idx & 15) << 2;
            *(float4*)&Qst[d * 64 + c] = *(const float4*)(src + (size_t)d * SQ_ + q0 + c);
        }
    }
    madd[tid & 511] = (1.0f - (float)mask[b * SK_ + (tid & 511)]) * (-3.402823466e38f);

    const int tq = tid >> 5;   // warp id 0..15 -> rows 4tq..4tq+3
    const int tk = tid & 31;   // lane -> 4 k cols within each 128 chunk

    // ---- Phase 1: scores, kept in registers across all 4 kc chunks ----
    float sreg[4][4][4];       // [kc][i(row)][jj(kcol)]

    for (int kc = 0; kc < 4; kc++) {
        __syncthreads();
        {   // load K chunk [d=64][k=128]
            const float* src = g_Kt + (size_t)bh * HD_ * SK_ + kc * 128;
            #pragma unroll
            for (int p = 0; p < 4; p++) {
                int idx = tid + p * 512;
                int d = idx >> 5;
                int c = (idx & 31) << 2;
                *(float4*)&KV[d * 128 + c] = *(const float4*)(src + (size_t)d * SK_ + c);
            }
        }
        __syncthreads();

        float acc[4][4];
        #pragma unroll
        for (int i = 0; i < 4; i++)
            #pragma unroll
            for (int j = 0; j < 4; j++) acc[i][j] = 0.0f;

        #pragma unroll 16
        for (int d = 0; d < 64; d++) {
            float4 a  = *(float4*)&Qst[d * 64 + tq * 4];
            float4 bb = *(float4*)&KV [d * 128 + tk * 4];
            float av[4] = {a.x, a.y, a.z, a.w};
            float bv[4] = {bb.x, bb.y, bb.z, bb.w};
            #pragma unroll
            for (int i = 0; i < 4; i++)
                #pragma unroll
                for (int j = 0; j < 4; j++)
                    acc[i][j] = fmaf(av[i], bv[j], acc[i][j]);
        }

        const size_t sbase = ((size_t)bh * SQ_ + q0) * SK_;
        #pragma unroll
        for (int i = 0; i < 4; i++) {
            int q = tq * 4 + i;
            float4 v = make_float4(acc[i][0], acc[i][1], acc[i][2], acc[i][3]);
            *(float4*)&out_scores[sbase + (size_t)q * SK_ + kc * 128 + tk * 4] = v;
            #pragma unroll
            for (int j = 0; j < 4; j++) sreg[kc][i][j] = acc[i][j];
        }
    }

    // ---- Phase 2: register softmax ----
    {
        float madd_r[4][4];
        #pragma unroll
        for (int kc = 0; kc < 4; kc++)
            #pragma unroll
            for (int j = 0; j < 4; j++)
                madd_r[kc][j] = madd[kc * 128 + tk * 4 + j];

        #pragma unroll
        for (int i = 0; i < 4; i++) {
            float mx = -3.402823466e38f;
            #pragma unroll
            for (int kc = 0; kc < 4; kc++)
                #pragma unroll
                for (int j = 0; j < 4; j++) {
                    sreg[kc][i][j] += madd_r[kc][j];
                    mx = fmaxf(mx, sreg[kc][i][j]);
                }
            #pragma unroll
            for (int o = 16; o > 0; o >>= 1)
                mx = fmaxf(mx, __shfl_xor_sync(0xffffffffu, mx, o));
            float s = 0.0f;
            #pragma unroll
            for (int kc = 0; kc < 4; kc++)
                #pragma unroll
                for (int j = 0; j < 4; j++) {
                    sreg[kc][i][j] = __expf(sreg[kc][i][j] - mx);
                    s += sreg[kc][i][j];
                }
            #pragma unroll
            for (int o = 16; o > 0; o >>= 1)
                s += __shfl_xor_sync(0xffffffffu, s, o);
            float inv = 1.0f / s;
            int q = tq * 4 + i;
            #pragma unroll
            for (int kc = 0; kc < 4; kc++) {
                float4 v = make_float4(sreg[kc][i][0] * inv, sreg[kc][i][1] * inv,
                                       sreg[kc][i][2] * inv, sreg[kc][i][3] * inv);
                *(float4*)&Ss[q * 512 + kc * 128 + tk * 4] = v;
            }
        }
    }

    // ---- Phase 3: context = P @ V ----
    // k-split 2: g = tid>>8 handles k-half [g*64, g*64+64) of each 128-chunk.
    // Thread (within group): qs = 0..15 (4 q rows), ds = 0..15 (4 d cols).
    // Inner loop steps k by 4: V via 4x LDS.128, P via 4x LDS.128 (one per q).
    const int g  = tid >> 8;        // 0,1
    const int t  = tid & 255;
    const int qs = t >> 4;          // q rows 4qs..4qs+3
    const int ds = t & 15;          // d cols 4ds..4ds+3

    float acc[4][4];
    #pragma unroll
    for (int i = 0; i < 4; i++)
        #pragma unroll
        for (int j = 0; j < 4; j++) acc[i][j] = 0.0f;

    for (int kc = 0; kc < 4; kc++) {
        __syncthreads();
        {   // load V chunk [k=128][d=64]
            const float* src = g_V + ((size_t)bh * SK_ + kc * 128) * HD_;
            #pragma unroll
            for (int p = 0; p < 4; p++) {
                int idx = tid + p * 512;
                int kk = idx >> 4;
                int c  = (idx & 15) << 2;
                *(float4*)&KV[kk * 64 + c] = *(const float4*)(src + (size_t)kk * 64 + c);
            }
        }
        __syncthreads();

        const int kbase = g * 64;
        #pragma unroll 4
        for (int k4 = 0; k4 < 64; k4 += 4) {
            const int kk = kbase + k4;
            float4 v0 = *(float4*)&KV[(kk + 0) * 64 + ds * 4];
            float4 v1 = *(float4*)&KV[(kk + 1) * 64 + ds * 4];
            float4 v2 = *(float4*)&KV[(kk + 2) * 64 + ds * 4];
            float4 v3 = *(float4*)&KV[(kk + 3) * 64 + ds * 4];
            #pragma unroll
            for (int i = 0; i < 4; i++) {
                float4 p = *(float4*)&Ss[(qs * 4 + i) * 512 + kc * 128 + kk];
                acc[i][0] = fmaf(p.x, v0.x, acc[i][0]);
                acc[i][1] = fmaf(p.x, v0.y, acc[i][1]);
                acc[i][2] = fmaf(p.x, v0.z, acc[i][2]);
                acc[i][3] = fmaf(p.x, v0.w, acc[i][3]);
                acc[i][0] = fmaf(p.y, v1.x, acc[i][0]);
                acc[i][1] = fmaf(p.y, v1.y, acc[i][1]);
                acc[i][2] = fmaf(p.y, v1.z, acc[i][2]);
                acc[i][3] = fmaf(p.y, v1.w, acc[i][3]);
                acc[i][0] = fmaf(p.z, v2.x, acc[i][0]);
                acc[i][1] = fmaf(p.z, v2.y, acc[i][1]);
                acc[i][2] = fmaf(p.z, v2.z, acc[i][2]);
                acc[i][3] = fmaf(p.z, v2.w, acc[i][3]);
                acc[i][0] = fmaf(p.w, v3.x, acc[i][0]);
                acc[i][1] = fmaf(p.w, v3.y, acc[i][1]);
                acc[i][2] = fmaf(p.w, v3.z, acc[i][2]);
                acc[i][3] = fmaf(p.w, v3.w, acc[i][3]);
            }
        }
    }

    // ---- k-split reduction (group 1 -> smem, group 0 adds & writes) ----
    __syncthreads();
    if (g == 1) {
        float* red = KV + t * 16;
        #pragma unroll
        for (int i = 0; i < 4; i++)
            *(float4*)&red[i * 4] = make_float4(acc[i][0], acc[i][1], acc[i][2], acc[i][3]);
    }
    __syncthreads();
    if (g == 0) {
        const float* red = KV + t * 16;
        #pragma unroll
        for (int i = 0; i < 4; i++) {
            float4 r = *(const float4*)&red[i * 4];
            int q = q0 + qs * 4 + i;
            float4 v = make_float4(acc[i][0] + r.x, acc[i][1] + r.y,
                                   acc[i][2] + r.z, acc[i][3] + r.w);
            *(float4*)&out_ctx[((size_t)b * SQ_ + q) * HID_ + h * 64 + ds * 4] = v;
        }
    }
}

// ---------------------------------------------------------------------------
extern "C" void kernel_launch(void* const* d_in, const int* in_sizes, int n_in,
                              void* d_out, int out_size)
{
    (void)in_sizes; (void)n_in; (void)out_size;
    const float* hs   = (const float*)d_in[0];
    const float* ehs  = (const float*)d_in[1];
    const int*   mask = (const int*)d_in[2];
    const float* Wq   = (const float*)d_in[3];
    const float* Wk   = (const float*)d_in[4];
    const float* Wv   = (const float*)d_in[5];

    float* out_ctx = (float*)d_out;
    float* out_sc  = out_ctx + (size_t)B_ * SQ_ * HID_;

    float *pQ, *pK, *pV;
    cudaGetSymbolAddress((void**)&pQ, g_Qt);
    cudaGetSymbolAddress((void**)&pK, g_Kt);
    cudaGetSymbolAddress((void**)&pV, g_V);

    const int attn_smem = (64*64 + 64*128 + 64*512 + 512) * 4;  // 182272 B
    cudaFuncSetAttribute(attn_kernel, cudaFuncAttributeMaxDynamicSharedMemorySize, attn_smem);

    // All three projections in ONE wave-packed kernel (384 CTAs)
    gemm_all<<<384, 256>>>(hs, ehs, Wq, Wk, Wv, pQ, pK, pV);

    // Fused attention
    dim3 ga(SQ_ / 64, NH_, B_);              // (32, 16, 2)
    attn_kernel<<<ga, 512, attn_smem>>>(mask, out_ctx, out_sc);
}

// round 9
// speedup vs baseline: 1.0025x; 1.0025x over previous
#include <cuda_runtime.h>
#include <cstdint>

#define B_   2
#define SQ_  2048
#define SK_  512
#define HID_ 1024
#define NH_  16
#define HD_  64

// Scratch (static __device__ globals: allowed, no runtime allocation)
__device__ float g_Qt[B_*NH_*HD_*SQ_];   // [bh][d][q], pre-scaled by 1/8
__device__ float g_Kt[B_*NH_*HD_*SK_];   // [bh][d][k]
__device__ float g_V [B_*NH_*SK_*HD_];   // [bh][k][d]

// ===================== packed f32x2 helpers (FFMA2) ========================
static __device__ __forceinline__ uint64_t pack2(float lo, float hi) {
    uint64_t r;
    asm("mov.b64 %0, {%1, %2};" : "=l"(r) : "f"(lo), "f"(hi));
    return r;
}
static __device__ __forceinline__ uint64_t dup2(float v) { return pack2(v, v); }
static __device__ __forceinline__ void fma2(uint64_t& d, uint64_t a, uint64_t b) {
    asm("fma.rn.f32x2 %0, %1, %2, %0;" : "+l"(d) : "l"(a), "l"(b));
}
static __device__ __forceinline__ void unpack2(uint64_t v, float& lo, float& hi) {
    asm("mov.b64 {%0, %1}, %2;" : "=f"(lo), "=f"(hi) : "l"(v));
}

// ---------------------------------------------------------------------------
// Unified QKV projection GEMM (UNCHANGED — measured at FFMA2 floor ~300us):
// out = A(M x 1024) @ W^T. 384 CTAs: [0,256)=Q, [256,320)=K, [320,384)=V.
// ---------------------------------------------------------------------------
__global__ void __launch_bounds__(256)
gemm_all(const float* __restrict__ hs, const float* __restrict__ ehs,
         const float* __restrict__ Wq, const float* __restrict__ Wk,
         const float* __restrict__ Wv,
         float* __restrict__ pQ, float* __restrict__ pK, float* __restrict__ pV)
{
    __shared__ float As[16][128];
    __shared__ float Bs[16][128];

    const int bid = blockIdx.x;
    const float *A, *W;
    float* outp;
    int S, mode, lx, ly;
    float scale;
    if (bid < 256) {
        A = hs;  W = Wq; outp = pQ; S = SQ_; scale = 0.125f; mode = 1;
        lx = bid & 7; ly = bid >> 3;
    } else if (bid < 320) {
        int t = bid - 256;
        A = ehs; W = Wk; outp = pK; S = SK_; scale = 1.0f; mode = 1;
        lx = t & 7; ly = t >> 3;
    } else {
        int t = bid - 320;
        A = ehs; W = Wv; outp = pV; S = SK_; scale = 1.0f; mode = 0;
        lx = t & 7; ly = t >> 3;
    }
    const int m0 = ly * 128;
    const int n0 = lx * 128;

    const int tid = threadIdx.x;
    const int tx  = tid & 15;
    const int ty  = tid >> 4;

    uint64_t acc2[8][4];
    #pragma unroll
    for (int i = 0; i < 8; i++)
        #pragma unroll
        for (int j = 0; j < 4; j++) acc2[i][j] = 0ull;

    for (int kt = 0; kt < HID_ / 16; kt++) {
        const float* Ap = A + (size_t)m0 * HID_ + kt * 16;
        const float* Wp = W + (size_t)n0 * HID_ + kt * 16;
        #pragma unroll
        for (int p = 0; p < 2; p++) {
            int idx = tid + p * 256;          // 0..511
            int row = idx >> 2;               // 0..127
            int c4  = (idx & 3) << 2;         // 0,4,8,12
            float4 va = *(const float4*)(Ap + (size_t)row * HID_ + c4);
            As[c4 + 0][row] = va.x; As[c4 + 1][row] = va.y;
            As[c4 + 2][row] = va.z; As[c4 + 3][row] = va.w;
            float4 vb = *(const float4*)(Wp + (size_t)row * HID_ + c4);
            Bs[c4 + 0][row] = vb.x; Bs[c4 + 1][row] = vb.y;
            Bs[c4 + 2][row] = vb.z; Bs[c4 + 3][row] = vb.w;
        }
        __syncthreads();

        #pragma unroll
        for (int k = 0; k < 16; k++) {
            float4 a0 = *(float4*)&As[k][ty * 4];
            float4 a1 = *(float4*)&As[k][64 + ty * 4];
            float4 b0 = *(float4*)&Bs[k][tx * 4];
            float4 b1 = *(float4*)&Bs[k][64 + tx * 4];
            uint64_t bp[4] = {pack2(b0.x, b0.y), pack2(b0.z, b0.w),
                              pack2(b1.x, b1.y), pack2(b1.z, b1.w)};
            float av[8] = {a0.x, a0.y, a0.z, a0.w, a1.x, a1.y, a1.z, a1.w};
            #pragma unroll
            for (int i = 0; i < 8; i++) {
                uint64_t ai = dup2(av[i]);
                #pragma unroll
                for (int j = 0; j < 4; j++)
                    fma2(acc2[i][j], ai, bp[j]);
            }
        }
        __syncthreads();
    }

    float acc[8][8];
    #pragma unroll
    for (int i = 0; i < 8; i++)
        #pragma unroll
        for (int j = 0; j < 4; j++)
            unpack2(acc2[i][j], acc[i][j * 2], acc[i][j * 2 + 1]);

    if (mode == 0) {
        #pragma unroll
        for (int i = 0; i < 8; i++) {
            int m  = m0 + ((i < 4) ? (ty * 4 + i) : (64 + ty * 4 + (i - 4)));
            int bb = m / S;
            int s  = m - bb * S;
            #pragma unroll
            for (int jg = 0; jg < 2; jg++) {
                int n = n0 + jg * 64 + tx * 4;
                int h = n >> 6, d = n & 63;
                float4 v = make_float4(acc[i][jg*4+0], acc[i][jg*4+1],
                                       acc[i][jg*4+2], acc[i][jg*4+3]);
                *(float4*)&outp[(((size_t)bb * NH_ + h) * S + s) * HD_ + d] = v;
            }
        }
    } else {
        #pragma unroll
        for (int jg = 0; jg < 2; jg++) {
            #pragma unroll
            for (int j = 0; j < 4; j++) {
                int n = n0 + jg * 64 + tx * 4 + j;
                int h = n >> 6, d = n & 63;
                #pragma unroll
                for (int ig = 0; ig < 2; ig++) {
                    int m  = m0 + ig * 64 + ty * 4;
                    int bb = m / S;
                    int s  = m - bb * S;
                    float4 v = make_float4(acc[ig*4+0][jg*4+j] * scale,
                                           acc[ig*4+1][jg*4+j] * scale,
                                           acc[ig*4+2][jg*4+j] * scale,
                                           acc[ig*4+3][jg*4+j] * scale);
                    *(float4*)&outp[(((size_t)bb * NH_ + h) * HD_ + d) * S + s] = v;
                }
            }
        }
    }
}

// ---------------------------------------------------------------------------
// Fused attention. Per block = one (b, h, 64-query tile), 512 threads.
// Phase 1: scores = Qs^T Ks (scalar FFMA), kept in regs, raw copy -> d_out.
// Phase 2: register softmax (warp owns its 4 rows), P -> smem once.
// Phase 3: context = P @ V — NEW: k-split 2, 4q x 4d per thread, k stepped by
//          4 so both P and V come in as LDS.128 (16 wf per 64 FMA).
// Dynamic smem 182272 B.
// ---------------------------------------------------------------------------
__global__ void __launch_bounds__(512)
attn_kernel(const int* __restrict__ mask,
            float* __restrict__ out_ctx, float* __restrict__ out_scores)
{
    extern __shared__ float smf[];
    float* Qst  = smf;                      // [64][64]  (d-major)
    float* KV   = smf + 64 * 64;            // [64][128] K chunk OR [128][64] V chunk
    float* Ss   = KV + 64 * 128;            // [64][512]  (holds P)
    float* madd = Ss + 64 * 512;            // [512]

    const int tid = threadIdx.x;
    const int q0  = blockIdx.x * 64;
    const int h   = blockIdx.y;
    const int b   = blockIdx.z;
    const int bh  = b * NH_ + h;

    {
        const float* src = g_Qt + (size_t)bh * HD_ * SQ_;
        #pragma unroll
        for (int p = 0; p < 2; p++) {
            int idx = tid + p * 512;
            int d = idx >> 4;
            int c = (idx & 15) << 2;
            *(float4*)&Qst[d * 64 + c] = *(const float4*)(src + (size_t)d * SQ_ + q0 + c);
        }
    }
    madd[tid & 511] = (1.0f - (float)mask[b * SK_ + (tid & 511)]) * (-3.402823466e38f);

    const int tq = tid >> 5;   // warp id 0..15 -> rows 4tq..4tq+3
    const int tk = tid & 31;   // lane -> 4 k cols within each 128 chunk

    // ---- Phase 1: scores, kept in registers across all 4 kc chunks ----
    float sreg[4][4][4];       // [kc][i(row)][jj(kcol)]

    for (int kc = 0; kc < 4; kc++) {
        __syncthreads();
        {   // load K chunk [d=64][k=128]
            const float* src = g_Kt + (size_t)bh * HD_ * SK_ + kc * 128;
            #pragma unroll
            for (int p = 0; p < 4; p++) {
                int idx = tid + p * 512;
                int d = idx >> 5;
                int c = (idx & 31) << 2;
                *(float4*)&KV[d * 128 + c] = *(const float4*)(src + (size_t)d * SK_ + c);
            }
        }
        __syncthreads();

        float acc[4][4];
        #pragma unroll
        for (int i = 0; i < 4; i++)
            #pragma unroll
            for (int j = 0; j < 4; j++) acc[i][j] = 0.0f;

        #pragma unroll 16
        for (int d = 0; d < 64; d++) {
            float4 a  = *(float4*)&Qst[d * 64 + tq * 4];
            float4 bb = *(float4*)&KV [d * 128 + tk * 4];
            float av[4] = {a.x, a.y, a.z, a.w};
            float bv[4] = {bb.x, bb.y, bb.z, bb.w};
            #pragma unroll
            for (int i = 0; i < 4; i++)
                #pragma unroll
                for (int j = 0; j < 4; j++)
                    acc[i][j] = fmaf(av[i], bv[j], acc[i][j]);
        }

        const size_t sbase = ((size_t)bh * SQ_ + q0) * SK_;
        #pragma unroll
        for (int i = 0; i < 4; i++) {
            int q = tq * 4 + i;
            float4 v = make_float4(acc[i][0], acc[i][1], acc[i][2], acc[i][3]);
            *(float4*)&out_scores[sbase + (size_t)q * SK_ + kc * 128 + tk * 4] = v;
            #pragma unroll
            for (int j = 0; j < 4; j++) sreg[kc][i][j] = acc[i][j];
        }
    }

    // ---- Phase 2: register softmax ----
    {
        float madd_r[4][4];
        #pragma unroll
        for (int kc = 0; kc < 4; kc++)
            #pragma unroll
            for (int j = 0; j < 4; j++)
                madd_r[kc][j] = madd[kc * 128 + tk * 4 + j];

        #pragma unroll
        for (int i = 0; i < 4; i++) {
            float mx = -3.402823466e38f;
            #pragma unroll
            for (int kc = 0; kc < 4; kc++)
                #pragma unroll
                for (int j = 0; j < 4; j++) {
                    sreg[kc][i][j] += madd_r[kc][j];
                    mx = fmaxf(mx, sreg[kc][i][j]);
                }
            #pragma unroll
            for (int o = 16; o > 0; o >>= 1)
                mx = fmaxf(mx, __shfl_xor_sync(0xffffffffu, mx, o));
            float s = 0.0f;
            #pragma unroll
            for (int kc = 0; kc < 4; kc++)
                #pragma unroll
                for (int j = 0; j < 4; j++) {
                    sreg[kc][i][j] = __expf(sreg[kc][i][j] - mx);
                    s += sreg[kc][i][j];
                }
            #pragma unroll
            for (int o = 16; o > 0; o >>= 1)
                s += __shfl_xor_sync(0xffffffffu, s, o);
            float inv = 1.0f / s;
            int q = tq * 4 + i;
            #pragma unroll
            for (int kc = 0; kc < 4; kc++) {
                float4 v = make_float4(sreg[kc][i][0] * inv, sreg[kc][i][1] * inv,
                                       sreg[kc][i][2] * inv, sreg[kc][i][3] * inv);
                *(float4*)&Ss[q * 512 + kc * 128 + tk * 4] = v;
            }
        }
    }

    // ---- Phase 3: context = P @ V ----
    // k-split 2: g = tid>>8 handles k-half [g*64, g*64+64) of each 128-chunk.
    // Thread (within group): qs = 0..15 (4 q rows), ds = 0..15 (4 d cols).
    // Inner loop steps k by 4: V via 4x LDS.128, P via 4x LDS.128 (one per q).
    const int g  = tid >> 8;        // 0,1
    const int t  = tid & 255;
    const int qs = t >> 4;          // q rows 4qs..4qs+3
    const int ds = t & 15;          // d cols 4ds..4ds+3

    float acc[4][4];
    #pragma unroll
    for (int i = 0; i < 4; i++)
        #pragma unroll
        for (int j = 0; j < 4; j++) acc[i][j] = 0.0f;

    for (int kc = 0; kc < 4; kc++) {
        __syncthreads();
        {   // load V chunk [k=128][d=64]
            const float* src = g_V + ((size_t)bh * SK_ + kc * 128) * HD_;
            #pragma unroll
            for (int p = 0; p < 4; p++) {
                int idx = tid + p * 512;
                int kk = idx >> 4;
                int c  = (idx & 15) << 2;
                *(float4*)&KV[kk * 64 + c] = *(const float4*)(src + (size_t)kk * 64 + c);
            }
        }
        __syncthreads();

        const int kbase = g * 64;
        #pragma unroll 4
        for (int k4 = 0; k4 < 64; k4 += 4) {
            const int kk = kbase + k4;
            float4 v0 = *(float4*)&KV[(kk + 0) * 64 + ds * 4];
            float4 v1 = *(float4*)&KV[(kk + 1) * 64 + ds * 4];
            float4 v2 = *(float4*)&KV[(kk + 2) * 64 + ds * 4];
            float4 v3 = *(float4*)&KV[(kk + 3) * 64 + ds * 4];
            #pragma unroll
            for (int i = 0; i < 4; i++) {
                float4 p = *(float4*)&Ss[(qs * 4 + i) * 512 + kc * 128 + kk];
                acc[i][0] = fmaf(p.x, v0.x, acc[i][0]);
                acc[i][1] = fmaf(p.x, v0.y, acc[i][1]);
                acc[i][2] = fmaf(p.x, v0.z, acc[i][2]);
                acc[i][3] = fmaf(p.x, v0.w, acc[i][3]);
                acc[i][0] = fmaf(p.y, v1.x, acc[i][0]);
                acc[i][1] = fmaf(p.y, v1.y, acc[i][1]);
                acc[i][2] = fmaf(p.y, v1.z, acc[i][2]);
                acc[i][3] = fmaf(p.y, v1.w, acc[i][3]);
                acc[i][0] = fmaf(p.z, v2.x, acc[i][0]);
                acc[i][1] = fmaf(p.z, v2.y, acc[i][1]);
                acc[i][2] = fmaf(p.z, v2.z, acc[i][2]);
                acc[i][3] = fmaf(p.z, v2.w, acc[i][3]);
                acc[i][0] = fmaf(p.w, v3.x, acc[i][0]);
                acc[i][1] = fmaf(p.w, v3.y, acc[i][1]);
                acc[i][2] = fmaf(p.w, v3.z, acc[i][2]);
                acc[i][3] = fmaf(p.w, v3.w, acc[i][3]);
            }
        }
    }

    // ---- k-split reduction (group 1 -> smem, group 0 adds & writes) ----
    __syncthreads();
    if (g == 1) {
        float* red = KV + t * 16;
        #pragma unroll
        for (int i = 0; i < 4; i++)
            *(float4*)&red[i * 4] = make_float4(acc[i][0], acc[i][1], acc[i][2], acc[i][3]);
    }
    __syncthreads();
    if (g == 0) {
        const float* red = KV + t * 16;
        #pragma unroll
        for (int i = 0; i < 4; i++) {
            float4 r = *(const float4*)&red[i * 4];
            int q = q0 + qs * 4 + i;
            float4 v = make_float4(acc[i][0] + r.x, acc[i][1] + r.y,
                                   acc[i][2] + r.z, acc[i][3] + r.w);
            *(float4*)&out_ctx[((size_t)b * SQ_ + q) * HID_ + h * 64 + ds * 4] = v;
        }
    }
}

// ---------------------------------------------------------------------------
extern "C" void kernel_launch(void* const* d_in, const int* in_sizes, int n_in,
                              void* d_out, int out_size)
{
    (void)in_sizes; (void)n_in; (void)out_size;
    const float* hs   = (const float*)d_in[0];
    const float* ehs  = (const float*)d_in[1];
    const int*   mask = (const int*)d_in[2];
    const float* Wq   = (const float*)d_in[3];
    const float* Wk   = (const float*)d_in[4];
    const float* Wv   = (const float*)d_in[5];

    float* out_ctx = (float*)d_out;
    float* out_sc  = out_ctx + (size_t)B_ * SQ_ * HID_;

    float *pQ, *pK, *pV;
    cudaGetSymbolAddress((void**)&pQ, g_Qt);
    cudaGetSymbolAddress((void**)&pK, g_Kt);
    cudaGetSymbolAddress((void**)&pV, g_V);

    const int attn_smem = (64*64 + 64*128 + 64*512 + 512) * 4;  // 182272 B
    cudaFuncSetAttribute(attn_kernel, cudaFuncAttributeMaxDynamicSharedMemorySize, attn_smem);

    // All three projections in ONE wave-packed kernel (384 CTAs)
    gemm_all<<<384, 256>>>(hs, ehs, Wq, Wk, Wv, pQ, pK, pV);

    // Fused attention
    dim3 ga(SQ_ / 64, NH_, B_);              // (32, 16, 2)
    attn_kernel<<<ga, 512, attn_smem>>>(mask, out_ctx, out_sc);
}